// round 4
// baseline (speedup 1.0000x reference)
#include <cuda_runtime.h>
#include <cuda_bf16.h>
#include <math.h>

// ---------------------------------------------------------------------------
// Problem constants
// ---------------------------------------------------------------------------
constexpr int Bb = 64;          // batch
constexpr int Nn = 128;         // nodes
constexpr int Dd = 256;         // hidden dim
constexpr int Ee = 4;           // edge types
constexpr int STEPS = 5;
constexpr int ANNOT = 64;
constexpr int Mrows = Bb * Nn;  // 8192
constexpr int EN = Ee * Nn;     // 512

constexpr long long OFF_NODE = 0;
constexpr long long OFF_EDGE = (long long)Mrows * ANNOT;                 // 524288
constexpr long long OFF_MU   = OFF_EDGE + (long long)Mrows * EN;         // 4718592
constexpr long long OFF_VAR  = OFF_MU + (long long)Mrows * Dd;           // 6815744

// ---------------------------------------------------------------------------
// Device scratch (static allocations — allowed)
// ---------------------------------------------------------------------------
__device__ float g_h0[Mrows * Dd];
__device__ float g_h1[Mrows * Dd];
__device__ float g_inst[Bb * EN * Dd];   // (b, m=e*N+n, d) layout
__device__ float g_ain[Mrows * Dd];
__device__ float g_r[Mrows * Dd];
__device__ float g_z[Mrows * Dd];
__device__ float g_t1[Mrows * Dd];
__device__ float g_t2[Mrows * Dd];
__device__ float g_zlat[Mrows * Dd];
__device__ float g_eps[Mrows * Dd];

// ---------------------------------------------------------------------------
// JAX threefry2x32, key = jax.random.key(42) -> (0, 42)
// ---------------------------------------------------------------------------
__device__ __forceinline__ unsigned rotl32(unsigned x, int r) {
    return (x << r) | (x >> (32 - r));
}

__device__ __forceinline__ void threefry2x32_42(unsigned& x0, unsigned& x1) {
    const unsigned ks0 = 0u, ks1 = 42u, ks2 = 0u ^ 42u ^ 0x1BD11BDAu;
    const unsigned ks[3] = {ks0, ks1, ks2};
    x0 += ks[0]; x1 += ks[1];
    const int R0[4] = {13, 15, 26, 6};
    const int R1[4] = {17, 29, 16, 24};
#pragma unroll
    for (int i = 0; i < 5; i++) {
#pragma unroll
        for (int j = 0; j < 4; j++) {
            int r = (i % 2 == 0) ? R0[j] : R1[j];
            x0 += x1;
            x1 = rotl32(x1, r);
            x1 ^= x0;
        }
        x0 += ks[(i + 1) % 3];
        x1 += ks[(i + 2) % 3] + (unsigned)(i + 1);
    }
}

// XLA ErfInv float32 polynomial (matches jax lax.erf_inv on f32)
__device__ __forceinline__ float erfinv_xla(float x) {
    float w = -log1pf(-x * x);
    float p;
    if (w < 5.0f) {
        w = w - 2.5f;
        p = 2.81022636e-08f;
        p = fmaf(p, w, 3.43273939e-07f);
        p = fmaf(p, w, -3.5233877e-06f);
        p = fmaf(p, w, -4.39150654e-06f);
        p = fmaf(p, w, 0.00021858087f);
        p = fmaf(p, w, -0.00125372503f);
        p = fmaf(p, w, -0.00417768164f);
        p = fmaf(p, w, 0.246640727f);
        p = fmaf(p, w, 1.50140941f);
    } else {
        w = sqrtf(w) - 3.0f;
        p = -0.000200214257f;
        p = fmaf(p, w, 0.000100950558f);
        p = fmaf(p, w, 0.00134934322f);
        p = fmaf(p, w, -0.00367342844f);
        p = fmaf(p, w, 0.00573950773f);
        p = fmaf(p, w, -0.0076224613f);
        p = fmaf(p, w, 0.00943887047f);
        p = fmaf(p, w, 1.00167406f);
        p = fmaf(p, w, 2.83297682f);
    }
    return p * x;
}

__device__ __forceinline__ float bits_to_normal(unsigned bits) {
    // jax.random.uniform(lo=nextafter(-1,0), hi=1), then sqrt(2)*erfinv
    float f = __uint_as_float((bits >> 9) | 0x3f800000u) - 1.0f;
    const float lo = -0.99999994f;
    const float range = 1.0f - lo;   // rounds to 2.0f in f32, matching XLA
    float u = __fmul_rn(f, range);
    u = __fadd_rn(u, lo);
    u = fmaxf(lo, u);
    return 1.4142135f * erfinv_xla(u);
}

// Partitionable threefry (jax_threefry_partitionable=True, modern default):
// per element i the counter is the 64-bit iota split as (hi,lo) = (0, i);
// for bit_width == 32 the two hash output lanes are XOR-folded:
//   out32 = bits1 ^ bits2   (jax/_src/prng.py, _threefry_random_bits_partitionable)
// [Rounds 2/3 tried each single lane and failed with rel_err ~ sqrt(2).]
__global__ void eps_kernel(float* __restrict__ eps) {
    unsigned i = blockIdx.x * blockDim.x + threadIdx.x;
    if (i >= (unsigned)(Mrows * Dd)) return;
    unsigned x0 = 0u, x1 = i;
    threefry2x32_42(x0, x1);
    eps[i] = bits_to_normal(x0 ^ x1);
}

// ---------------------------------------------------------------------------
// Generic tiled SGEMM: 64x64 tile, BK=16, 256 threads, 4x4 per thread.
// Spec supplies loadA(row,k,bz), loadB(k,col,bz), store(row,col,v,bz).
// ---------------------------------------------------------------------------
template <class Spec>
__global__ void __launch_bounds__(256) gemm_k(Spec s, int M, int Ncols, int K) {
    __shared__ __align__(16) float As[16][68];  // [k][m]
    __shared__ __align__(16) float Bs[16][68];  // [k][n]

    const int bz = blockIdx.z;
    const int row0 = blockIdx.y * 64;
    const int col0 = blockIdx.x * 64;
    const int tid = threadIdx.x;
    const int lk = tid & 15, lm = tid >> 4;   // A-tile loader
    const int ln = tid & 63, lk2 = tid >> 6;  // B-tile loader
    const int tx = tid & 15, ty = tid >> 4;   // compute mapping

    float acc[4][4] = {};

    for (int k0 = 0; k0 < K; k0 += 16) {
#pragma unroll
        for (int i = 0; i < 4; i++)
            As[lk][lm + 16 * i] = s.loadA(row0 + lm + 16 * i, k0 + lk, bz);
#pragma unroll
        for (int j = 0; j < 4; j++)
            Bs[lk2 + 4 * j][ln] = s.loadB(k0 + lk2 + 4 * j, col0 + ln, bz);
        __syncthreads();
#pragma unroll
        for (int kk = 0; kk < 16; kk++) {
            float4 a4 = *(const float4*)&As[kk][ty * 4];
            float4 b4 = *(const float4*)&Bs[kk][tx * 4];
            float av[4] = {a4.x, a4.y, a4.z, a4.w};
            float bv[4] = {b4.x, b4.y, b4.z, b4.w};
#pragma unroll
            for (int i = 0; i < 4; i++)
#pragma unroll
                for (int j = 0; j < 4; j++)
                    acc[i][j] = fmaf(av[i], bv[j], acc[i][j]);
        }
        __syncthreads();
    }

#pragma unroll
    for (int i = 0; i < 4; i++)
#pragma unroll
        for (int j = 0; j < 4; j++)
            s.store(row0 + ty * 4 + i, col0 + tx * 4 + j, acc[i][j], bz);
}

__device__ __forceinline__ float sigmoidf_(float x) { return 1.0f / (1.0f + expf(-x)); }

// --- Stage 1: in_states[b, e*N+n, f] = h[b,n,:] @ W_in[e] + b_in[e]  ---------
struct SpecInstates {
    const float* h; const float* W_in; const float* b_in; float* out;
    __device__ float loadA(int row, int k, int) const { return h[row * Dd + k]; }
    __device__ float loadB(int k, int col, int) const {
        int e = col >> 8, f = col & 255;
        return W_in[(e * Dd + k) * Dd + f];
    }
    __device__ void store(int row, int col, float v, int) const {
        int e = col >> 8, f = col & 255;
        int b = row >> 7, n = row & 127;
        out[((long long)b * EN + (e * Nn + n)) * Dd + f] = v + b_in[e * Dd + f];
    }
};

// --- Stage 2 (batched): a_in[b] = A_in[b] (128x512) @ in_states[b] (512x256) -
struct SpecAin {
    const float* A; const float* inst; float* out;
    __device__ float loadA(int row, int k, int b) const {
        return A[((long long)b * Nn + row) * (2 * EN) + k];
    }
    __device__ float loadB(int k, int col, int b) const {
        return inst[((long long)b * EN + k) * Dd + col];
    }
    __device__ void store(int row, int col, float v, int b) const {
        out[((long long)b * Nn + row) * Dd + col] = v;
    }
};

// --- Stage 3: r,z = sigmoid([a_in | h] @ [W_r | W_z] + [b_r | b_z]) ----------
struct SpecGates {
    const float* ain; const float* h;
    const float* W_r; const float* W_z; const float* b_r; const float* b_z;
    float* rb; float* zb;
    __device__ float loadA(int row, int k, int) const {
        return (k < Dd) ? ain[row * Dd + k] : h[row * Dd + (k - Dd)];
    }
    __device__ float loadB(int k, int col, int) const {
        return (col < Dd) ? W_r[k * Dd + col] : W_z[k * Dd + (col - Dd)];
    }
    __device__ void store(int row, int col, float v, int) const {
        if (col < Dd) rb[row * Dd + col] = sigmoidf_(v + b_r[col]);
        else          zb[row * Dd + (col - Dd)] = sigmoidf_(v + b_z[col - Dd]);
    }
};

// --- Stage 4: h_hat = tanh([a_in | r*h] @ W_t + b_t); h' = (1-z)h + z*h_hat --
struct SpecHhat {
    const float* ain; const float* rb; const float* hin;
    const float* W_t; const float* b_t; const float* zb;
    float* hout;
    __device__ float loadA(int row, int k, int) const {
        if (k < Dd) return ain[row * Dd + k];
        int idx = row * Dd + (k - Dd);
        return rb[idx] * hin[idx];
    }
    __device__ float loadB(int k, int col, int) const { return W_t[k * Dd + col]; }
    __device__ void store(int row, int col, float v, int) const {
        float hh = tanhf(v + b_t[col]);
        int idx = row * Dd + col;
        float z = zb[idx];
        hout[idx] = (1.0f - z) * hin[idx] + z * hh;
    }
};

// --- Head a: t1 = tanh(h@W_mu1+b), t2 = tanh(h@W_var1+b) ---------------------
struct SpecMuVarT {
    const float* h;
    const float* W1; const float* W2; const float* b1; const float* b2;
    float* t1; float* t2;
    __device__ float loadA(int row, int k, int) const { return h[row * Dd + k]; }
    __device__ float loadB(int k, int col, int) const {
        return (col < Dd) ? W1[k * Dd + col] : W2[k * Dd + (col - Dd)];
    }
    __device__ void store(int row, int col, float v, int) const {
        if (col < Dd) t1[row * Dd + col] = tanhf(v + b1[col]);
        else          t2[row * Dd + (col - Dd)] = tanhf(v + b2[col - Dd]);
    }
};

// --- Head b: plain linear: out = X @ W + b -----------------------------------
struct SpecLin {
    const float* X; const float* W; const float* bias; float* out;
    __device__ float loadA(int row, int k, int) const { return X[row * Dd + k]; }
    __device__ float loadB(int k, int col, int) const { return W[k * Dd + col]; }
    __device__ void store(int row, int col, float v, int) const {
        out[(long long)row * Dd + col] = v + bias[col];
    }
};

// --- Head d: node/edge decode: zlat @ [W_d1 | W_d2] --------------------------
struct SpecDecode {
    const float* zl;
    const float* W_d1; const float* W_d2; const float* b_d1; const float* b_d2;
    float* node; float* edge;
    __device__ float loadA(int row, int k, int) const { return zl[row * Dd + k]; }
    __device__ float loadB(int k, int col, int) const {
        return (col < ANNOT) ? W_d1[k * ANNOT + col] : W_d2[k * EN + (col - ANNOT)];
    }
    __device__ void store(int row, int col, float v, int) const {
        if (col < ANNOT) node[(long long)row * ANNOT + col] = v + b_d1[col];
        else             edge[(long long)row * EN + (col - ANNOT)] = v + b_d2[col - ANNOT];
    }
};

// --- zlat = eps * exp(0.5*var) + mu ------------------------------------------
__global__ void zlat_kernel(const float* __restrict__ eps,
                            const float* __restrict__ mu,
                            const float* __restrict__ var,
                            float* __restrict__ zl) {
    int i = blockIdx.x * blockDim.x + threadIdx.x;
    if (i >= Mrows * Dd) return;
    zl[i] = eps[i] * expf(0.5f * var[i]) + mu[i];
}

// ---------------------------------------------------------------------------
// Launch
// ---------------------------------------------------------------------------
extern "C" void kernel_launch(void* const* d_in, const int* in_sizes, int n_in,
                              void* d_out, int out_size) {
    // Input binding. Primary assumption: metadata preserves the setup_inputs()
    // dict (insertion) order. Fingerprint check: prop_state has 2097152 elems.
    // Fallback: alphabetical key order.
    const float* in[22];
    if (in_sizes[0] == Mrows * Dd) {
        for (int i = 0; i < 22; i++) in[i] = (const float*)d_in[i];
    } else {
        // alpha order: A,W_d1,W_d2,W_in,W_mu1,W_mu2,W_r,W_t,W_var1,W_var2,W_z,
        //              b_d1,b_d2,b_in,b_mu1,b_mu2,b_r,b_t,b_var1,b_var2,b_z,prop
        static const int alphaOfDict[22] = {21, 0, 3, 13, 6, 16, 10, 20, 7, 17,
                                            4, 14, 5, 15, 8, 18, 9, 19, 1, 11,
                                            2, 12};
        for (int i = 0; i < 22; i++) in[i] = (const float*)d_in[alphaOfDict[i]];
    }
    const float* prop  = in[0];
    const float* A     = in[1];
    const float* W_in  = in[2];
    const float* b_in  = in[3];
    const float* W_r   = in[4];
    const float* b_r   = in[5];
    const float* W_z   = in[6];
    const float* b_z   = in[7];
    const float* W_t   = in[8];
    const float* b_t   = in[9];
    const float* W_mu1 = in[10];
    const float* b_mu1 = in[11];
    const float* W_mu2 = in[12];
    const float* b_mu2 = in[13];
    const float* W_var1 = in[14];
    const float* b_var1 = in[15];
    const float* W_var2 = in[16];
    const float* b_var2 = in[17];
    const float* W_d1  = in[18];
    const float* b_d1  = in[19];
    const float* W_d2  = in[20];
    const float* b_d2  = in[21];
    float* out = (float*)d_out;

    float *h0, *h1, *inst, *ain, *rb, *zb, *t1, *t2, *zl, *eps;
    cudaGetSymbolAddress((void**)&h0, g_h0);
    cudaGetSymbolAddress((void**)&h1, g_h1);
    cudaGetSymbolAddress((void**)&inst, g_inst);
    cudaGetSymbolAddress((void**)&ain, g_ain);
    cudaGetSymbolAddress((void**)&rb, g_r);
    cudaGetSymbolAddress((void**)&zb, g_z);
    cudaGetSymbolAddress((void**)&t1, g_t1);
    cudaGetSymbolAddress((void**)&t2, g_t2);
    cudaGetSymbolAddress((void**)&zl, g_zlat);
    cudaGetSymbolAddress((void**)&eps, g_eps);

    // h0 <- prop_state
    cudaMemcpyAsync(h0, prop, (size_t)Mrows * Dd * sizeof(float),
                    cudaMemcpyDeviceToDevice);

    // eps (deterministic, input independent)
    eps_kernel<<<(Mrows * Dd + 255) / 256, 256>>>(eps);

    for (int step = 0; step < STEPS; step++) {
        float* hin  = (step % 2 == 0) ? h0 : h1;
        float* hout = (step % 2 == 0) ? h1 : h0;

        gemm_k<<<dim3(Ee * Dd / 64, Mrows / 64, 1), 256>>>(
            SpecInstates{hin, W_in, b_in, inst}, Mrows, Ee * Dd, Dd);

        gemm_k<<<dim3(Dd / 64, Nn / 64, Bb), 256>>>(
            SpecAin{A, inst, ain}, Nn, Dd, EN);

        gemm_k<<<dim3(2 * Dd / 64, Mrows / 64, 1), 256>>>(
            SpecGates{ain, hin, W_r, W_z, b_r, b_z, rb, zb}, Mrows, 2 * Dd, 2 * Dd);

        gemm_k<<<dim3(Dd / 64, Mrows / 64, 1), 256>>>(
            SpecHhat{ain, rb, hin, W_t, b_t, zb, hout}, Mrows, Dd, 2 * Dd);
    }
    float* hfin = h1;  // STEPS=5 -> ends in h1

    gemm_k<<<dim3(2 * Dd / 64, Mrows / 64, 1), 256>>>(
        SpecMuVarT{hfin, W_mu1, W_var1, b_mu1, b_var1, t1, t2}, Mrows, 2 * Dd, Dd);

    gemm_k<<<dim3(Dd / 64, Mrows / 64, 1), 256>>>(
        SpecLin{t1, W_mu2, b_mu2, out + OFF_MU}, Mrows, Dd, Dd);

    gemm_k<<<dim3(Dd / 64, Mrows / 64, 1), 256>>>(
        SpecLin{t2, W_var2, b_var2, out + OFF_VAR}, Mrows, Dd, Dd);

    zlat_kernel<<<(Mrows * Dd + 255) / 256, 256>>>(eps, out + OFF_MU,
                                                   out + OFF_VAR, zl);

    gemm_k<<<dim3((ANNOT + EN) / 64, Mrows / 64, 1), 256>>>(
        SpecDecode{zl, W_d1, W_d2, b_d1, b_d2, out + OFF_NODE, out + OFF_EDGE},
        Mrows, ANNOT + EN, Dd);
}